// round 2
// baseline (speedup 1.0000x reference)
#include <cuda_runtime.h>

#define BB 512
#define TT 1024
#define HH 100
#define VV 62
#define NL 3

// ping-pong time-major [T][B][H] activation buffers (no cudaMalloc allowed)
__device__ float g_bufA[(size_t)TT * BB * HH];
__device__ float g_bufB[(size_t)TT * BB * HH];

// fast tanh: 1 - 2/(e^{2x}+1). __expf overflow -> inf -> 2/inf = 0 -> 1. OK at both ends.
__device__ __forceinline__ float ftanh(float x) {
    float e = __expf(x + x);
    return 1.0f - __fdividef(2.0f, e + 1.0f);
}

// ---------------------------------------------------------------------------
// input projection (optionally fused with embedding gather for layer 0):
//   Y[row][k] = sum_j X[row][j]*W[k][j] + bi[k] + bh[k],  rows = T*B time-major
// 400 threads = 25 k-quads x 16 row-groups, 64 rows/block, zero k padding.
// Each thread: 4k x 4row register tile, float4 loads of W rows (no transpose).
// ---------------------------------------------------------------------------
template <bool FUSE_EMB>
__global__ void __launch_bounds__(400) k_proj(const float* __restrict__ X,
                                              const int* __restrict__ ids,
                                              const float* __restrict__ emb,
                                              const float* __restrict__ W,
                                              const float* __restrict__ bi,
                                              const float* __restrict__ bh,
                                              float* __restrict__ Y) {
    extern __shared__ float sm[];
    float* Ws = sm;            // [100][100] as-is  (10000 floats)
    float* Xs = sm + 10000;    // [64][100]         (6400 floats)
    float* bs = sm + 16400;    // [100]

    int tid = threadIdx.x;
    float4* Ws4 = (float4*)Ws;
    const float4* Wg = (const float4*)W;
    for (int i = tid; i < 2500; i += 400) Ws4[i] = Wg[i];
    if (tid < HH) bs[tid] = bi[tid] + bh[tid];

    size_t row0 = (size_t)blockIdx.x * 64;
    float4* Xs4 = (float4*)Xs;
    for (int i = tid; i < 64 * 25; i += 400) {
        int r = i / 25, c = i % 25;
        size_t row = row0 + r;
        const float4* src;
        if (FUSE_EMB) {
            int t = (int)(row >> 9);
            int b = (int)(row & 511);
            int id = ids[(size_t)b * TT + t];
            src = (const float4*)(emb + (size_t)id * HH);
        } else {
            src = (const float4*)(X + row * HH);
        }
        Xs4[r * 25 + c] = src[c];
    }
    __syncthreads();

    int kq = tid % 25;   // k quad: k = 4*kq .. 4*kq+3
    int rg = tid / 25;   // 0..15
    int r0 = rg * 4;

    float4 b4 = ((const float4*)bs)[kq];
    float acc[4][4];
#pragma unroll
    for (int rr = 0; rr < 4; rr++) {
        acc[rr][0] = b4.x; acc[rr][1] = b4.y; acc[rr][2] = b4.z; acc[rr][3] = b4.w;
    }

#pragma unroll 5
    for (int j4 = 0; j4 < 25; j4++) {
        float4 w0 = Ws4[(kq * 4 + 0) * 25 + j4];
        float4 w1 = Ws4[(kq * 4 + 1) * 25 + j4];
        float4 w2 = Ws4[(kq * 4 + 2) * 25 + j4];
        float4 w3 = Ws4[(kq * 4 + 3) * 25 + j4];
#pragma unroll
        for (int rr = 0; rr < 4; rr++) {
            float4 x = Xs4[(r0 + rr) * 25 + j4];
            acc[rr][0] += x.x * w0.x + x.y * w0.y + x.z * w0.z + x.w * w0.w;
            acc[rr][1] += x.x * w1.x + x.y * w1.y + x.z * w1.z + x.w * w1.w;
            acc[rr][2] += x.x * w2.x + x.y * w2.y + x.z * w2.z + x.w * w2.w;
            acc[rr][3] += x.x * w3.x + x.y * w3.y + x.z * w3.z + x.w * w3.w;
        }
    }

    float4* Yg = (float4*)Y;
#pragma unroll
    for (int rr = 0; rr < 4; rr++) {
        float4 o;
        o.x = acc[rr][0]; o.y = acc[rr][1]; o.z = acc[rr][2]; o.w = acc[rr][3];
        Yg[(row0 + r0 + rr) * 25 + kq] = o;
    }
}

// ---------------------------------------------------------------------------
// recurrent scan (per layer), in-place on XY (time-major [T][B][H]):
//   h_new = tanh(xin[t] + h @ Wh^T)
// 2 batch rows/block, 256 blocks (~2 blocks/SM), double-buffered h ->
// ONE __syncthreads per step. xin prefetched one step ahead.
// ---------------------------------------------------------------------------
__global__ void __launch_bounds__(128) k_rnn(float* __restrict__ XY,
                                             const float* __restrict__ W,
                                             float* __restrict__ hout) {
    __shared__ float Ws[HH * HH];      // [k][j]
    __shared__ float hs[2][2][104];    // [buf][row][k]

    int tid = threadIdx.x;
    float4* Ws4 = (float4*)Ws;
    const float4* Wg = (const float4*)W;
    for (int i = tid; i < 2500; i += 128) Ws4[i] = Wg[i];
    if (tid < 104) { hs[0][0][tid] = 0.f; hs[0][1][tid] = 0.f; }
    __syncthreads();

    int k  = tid;
    int kk = (k < HH) ? k : (HH - 1);
    int b0 = blockIdx.x * 2;
    const float4* wrow = (const float4*)(Ws + kk * HH);
    const size_t st = (size_t)BB * HH;
    const float* px = XY + (size_t)b0 * HH + kk;

    float c0 = px[0], c1 = px[HH];
    int p = 0;

    for (int t = 0; t < TT; t++) {
        size_t tn = (size_t)((t + 1 < TT) ? t + 1 : t) * st;
        float n0 = px[tn], n1 = px[tn + HH];

        float a0 = c0, a1 = c1;
#pragma unroll
        for (int j4 = 0; j4 < 25; j4++) {
            float4 w  = wrow[j4];
            float4 h0 = *(const float4*)(&hs[p][0][j4 * 4]);
            float4 h1 = *(const float4*)(&hs[p][1][j4 * 4]);
            a0 += w.x * h0.x + w.y * h0.y + w.z * h0.z + w.w * h0.w;
            a1 += w.x * h1.x + w.y * h1.y + w.z * h1.z + w.w * h1.w;
        }
        a0 = ftanh(a0); a1 = ftanh(a1);

        if (k < HH) {
            hs[p ^ 1][0][k] = a0;
            hs[p ^ 1][1][k] = a1;
            float* py = XY + (size_t)t * st + (size_t)b0 * HH + k;
            py[0] = a0; py[HH] = a1;
        }
        __syncthreads();   // writes to buf p^1 visible; everyone done reading buf p
        p ^= 1;
        c0 = n0; c1 = n1;
    }

    if (k < HH) {
        hout[(size_t)(b0 + 0) * HH + k] = hs[p][0][k];
        hout[(size_t)(b0 + 1) * HH + k] = hs[p][1][k];
    }
}

// ---------------------------------------------------------------------------
// decoder: logits[b][t][v] = dot(ys[t][b][:], Wd[v][:]) + bd[v]
// 256 threads = 16 v-quads (V padded to 64) x 16 row-groups, 64 rows/block.
// ---------------------------------------------------------------------------
__global__ void __launch_bounds__(256) k_dec(const float* __restrict__ Ys,
                                             const float* __restrict__ Wd,
                                             const float* __restrict__ bd,
                                             float* __restrict__ out) {
    extern __shared__ float sm[];
    float* Ws = sm;            // [64][100] padded
    float* Xs = sm + 6400;     // [64][100]
    float* bs = sm + 12800;    // [64]

    int tid = threadIdx.x;
    for (int i = tid; i < 6400; i += 256) Ws[i] = (i < VV * HH) ? Wd[i] : 0.f;
    if (tid < 64) bs[tid] = (tid < VV) ? bd[tid] : 0.f;

    size_t row0 = (size_t)blockIdx.x * 64;
    float4* Xs4 = (float4*)Xs;
    const float4* Yg = (const float4*)Ys;
    for (int i = tid; i < 64 * 25; i += 256) Xs4[i] = Yg[row0 * 25 + i];
    __syncthreads();

    int vq = tid % 16;   // v = 4*vq .. 4*vq+3
    int rg = tid / 16;   // 0..15
    int r0 = rg * 4;

    float4* Ws4 = (float4*)Ws;
    float4 b4 = ((const float4*)bs)[vq];
    float acc[4][4];
#pragma unroll
    for (int rr = 0; rr < 4; rr++) {
        acc[rr][0] = b4.x; acc[rr][1] = b4.y; acc[rr][2] = b4.z; acc[rr][3] = b4.w;
    }

#pragma unroll 5
    for (int j4 = 0; j4 < 25; j4++) {
        float4 w0 = Ws4[(vq * 4 + 0) * 25 + j4];
        float4 w1 = Ws4[(vq * 4 + 1) * 25 + j4];
        float4 w2 = Ws4[(vq * 4 + 2) * 25 + j4];
        float4 w3 = Ws4[(vq * 4 + 3) * 25 + j4];
#pragma unroll
        for (int rr = 0; rr < 4; rr++) {
            float4 x = Xs4[(r0 + rr) * 25 + j4];
            acc[rr][0] += x.x * w0.x + x.y * w0.y + x.z * w0.z + x.w * w0.w;
            acc[rr][1] += x.x * w1.x + x.y * w1.y + x.z * w1.z + x.w * w1.w;
            acc[rr][2] += x.x * w2.x + x.y * w2.y + x.z * w2.z + x.w * w2.w;
            acc[rr][3] += x.x * w3.x + x.y * w3.y + x.z * w3.z + x.w * w3.w;
        }
    }

#pragma unroll
    for (int rr = 0; rr < 4; rr++) {
        size_t row = row0 + r0 + rr;          // = t*BB + b
        size_t t = row >> 9;
        size_t b = row & 511;
        float* o = out + (b * TT + t) * VV + vq * 4;
        o[0] = acc[rr][0];
        o[1] = acc[rr][1];
        if (vq < 15) { o[2] = acc[rr][2]; o[3] = acc[rr][3]; }
    }
}

// ---------------------------------------------------------------------------
extern "C" void kernel_launch(void* const* d_in, const int* in_sizes, int n_in,
                              void* d_out, int out_size) {
    const int*   ids   = (const int*)d_in[0];
    const float* emb   = (const float*)d_in[1];
    const float* W_ih  = (const float*)d_in[2];   // [3][100][100]
    const float* W_hh  = (const float*)d_in[3];   // [3][100][100]
    const float* b_ih  = (const float*)d_in[4];   // [3][100]
    const float* b_hh  = (const float*)d_in[5];   // [3][100]
    const float* W_dec = (const float*)d_in[6];   // [62][100]
    const float* b_dec = (const float*)d_in[7];   // [62]
    float* out = (float*)d_out;

    float *bufA, *bufB;
    cudaGetSymbolAddress((void**)&bufA, g_bufA);
    cudaGetSymbolAddress((void**)&bufB, g_bufB);

    const int proj_smem = 16500 * (int)sizeof(float);   // 66 KB
    const int dec_smem  = 12864 * (int)sizeof(float);   // ~50.3 KB
    cudaFuncSetAttribute(k_proj<true>,  cudaFuncAttributeMaxDynamicSharedMemorySize, proj_smem);
    cudaFuncSetAttribute(k_proj<false>, cudaFuncAttributeMaxDynamicSharedMemorySize, proj_smem);
    cudaFuncSetAttribute(k_dec, cudaFuncAttributeMaxDynamicSharedMemorySize, dec_smem);

    float* hid = out + (size_t)BB * TT * VV;
    const int NPROJ = (TT * BB) / 64;   // 8192

    // layer 0 (embedding fused into proj)
    k_proj<true><<<NPROJ, 400, proj_smem>>>(nullptr, ids, emb, W_ih, b_ih, b_hh, bufA);
    k_rnn<<<BB / 2, 128>>>(bufA, W_hh, hid);

    // layer 1
    k_proj<false><<<NPROJ, 400, proj_smem>>>(bufA, nullptr, nullptr,
                                             W_ih + 10000, b_ih + 100, b_hh + 100, bufB);
    k_rnn<<<BB / 2, 128>>>(bufB, W_hh + 10000, hid + (size_t)BB * HH);

    // layer 2
    k_proj<false><<<NPROJ, 400, proj_smem>>>(bufB, nullptr, nullptr,
                                             W_ih + 20000, b_ih + 200, b_hh + 200, bufA);
    k_rnn<<<BB / 2, 128>>>(bufA, W_hh + 20000, hid + 2 * (size_t)BB * HH);

    // decoder
    k_dec<<<NPROJ, 256, dec_smem>>>(bufA, W_dec, b_dec, out);
}

// round 3
// speedup vs baseline: 1.7755x; 1.7755x over previous
#include <cuda_runtime.h>

#define BB 512
#define TT 1024
#define HH 100
#define VV 62

typedef unsigned long long ull;

// ping-pong time-major [T][B][H] activation buffers (no cudaMalloc allowed)
__device__ float g_bufA[(size_t)TT * BB * HH];
__device__ float g_bufB[(size_t)TT * BB * HH];

// packed dual-fp32 FMA: d.lo += a.lo*b.lo ; d.hi += a.hi*b.hi
__device__ __forceinline__ void fma2(ull& d, ull a, ull b) {
    asm("fma.rn.f32x2 %0, %1, %2, %0;" : "+l"(d) : "l"(a), "l"(b));
}
__device__ __forceinline__ float red2(ull v) {
    return __uint_as_float((unsigned)v) + __uint_as_float((unsigned)(v >> 32));
}
// fast tanh: 1 - 2/(e^{2x}+1); handles +-inf correctly via __expf saturation
__device__ __forceinline__ float ftanh(float x) {
    float e = __expf(x + x);
    return 1.0f - __fdividef(2.0f, e + 1.0f);
}

// ---------------------------------------------------------------------------
// 1) embedding gather: x[t][b][:] = emb[ids[b][t]][:]  (time-major out)
// ---------------------------------------------------------------------------
__global__ void k_gather(const int* __restrict__ ids,
                         const float* __restrict__ emb,
                         float* __restrict__ out) {
    int idx = blockIdx.x * blockDim.x + threadIdx.x;  // over T*B*25 float4
    if (idx >= TT * BB * 25) return;
    int c  = idx % 25;
    int tb = idx / 25;
    int b  = tb % BB;
    int t  = tb / BB;
    int id = ids[(size_t)b * TT + t];
    float4 v = ((const float4*)(emb + (size_t)id * HH))[c];
    ((float4*)(out + ((size_t)t * BB + b) * HH))[c] = v;
}

// ---------------------------------------------------------------------------
// 2) input projection: Y[row][k] = sum_j X[row][j]*W[k][j] + bi[k] + bh[k]
// 400 thr = 25 k-quads (kq=tid/16 -> W loads phase-broadcast) x 16 row-groups
// rows r = rg + 16*rr (stride-16 -> X loads conflict-free). FFMA2 4x4 tile.
// ---------------------------------------------------------------------------
__global__ void __launch_bounds__(400, 2) k_proj(const float* __restrict__ X,
                                                 const float* __restrict__ W,
                                                 const float* __restrict__ bi,
                                                 const float* __restrict__ bh,
                                                 float* __restrict__ Y) {
    extern __shared__ float sm[];
    float* Ws = sm;            // [100][100]
    float* Xs = sm + 10000;    // [64][100]
    float* bs = sm + 16400;    // [100]

    int tid = threadIdx.x;
    float4* Ws4 = (float4*)Ws;
    const float4* Wg = (const float4*)W;
    for (int i = tid; i < 2500; i += 400) Ws4[i] = Wg[i];
    if (tid < HH) bs[tid] = bi[tid] + bh[tid];

    size_t row0 = (size_t)blockIdx.x * 64;
    float4* Xs4 = (float4*)Xs;
    const float4* Xg = (const float4*)X;
    for (int i = tid; i < 1600; i += 400) Xs4[i] = Xg[row0 * 25 + i];
    __syncthreads();

    int kq = tid / 16;   // 0..24 (uniform over 16-lane groups -> broadcast W)
    int rg = tid % 16;

    const ulonglong2* Wu = (const ulonglong2*)Ws;  // same indexing as float4
    const ulonglong2* Xu = (const ulonglong2*)Xs;

    ull acc[4][4];
#pragma unroll
    for (int c = 0; c < 4; c++)
#pragma unroll
        for (int r = 0; r < 4; r++) acc[c][r] = 0ull;

#pragma unroll 5
    for (int j4 = 0; j4 < 25; j4++) {
        ulonglong2 w0 = Wu[(kq * 4 + 0) * 25 + j4];
        ulonglong2 w1 = Wu[(kq * 4 + 1) * 25 + j4];
        ulonglong2 w2 = Wu[(kq * 4 + 2) * 25 + j4];
        ulonglong2 w3 = Wu[(kq * 4 + 3) * 25 + j4];
        ulonglong2 x0 = Xu[(rg +  0) * 25 + j4];
        ulonglong2 x1 = Xu[(rg + 16) * 25 + j4];
        ulonglong2 x2 = Xu[(rg + 32) * 25 + j4];
        ulonglong2 x3 = Xu[(rg + 48) * 25 + j4];
        fma2(acc[0][0], w0.x, x0.x); fma2(acc[0][0], w0.y, x0.y);
        fma2(acc[1][0], w1.x, x0.x); fma2(acc[1][0], w1.y, x0.y);
        fma2(acc[2][0], w2.x, x0.x); fma2(acc[2][0], w2.y, x0.y);
        fma2(acc[3][0], w3.x, x0.x); fma2(acc[3][0], w3.y, x0.y);
        fma2(acc[0][1], w0.x, x1.x); fma2(acc[0][1], w0.y, x1.y);
        fma2(acc[1][1], w1.x, x1.x); fma2(acc[1][1], w1.y, x1.y);
        fma2(acc[2][1], w2.x, x1.x); fma2(acc[2][1], w2.y, x1.y);
        fma2(acc[3][1], w3.x, x1.x); fma2(acc[3][1], w3.y, x1.y);
        fma2(acc[0][2], w0.x, x2.x); fma2(acc[0][2], w0.y, x2.y);
        fma2(acc[1][2], w1.x, x2.x); fma2(acc[1][2], w1.y, x2.y);
        fma2(acc[2][2], w2.x, x2.x); fma2(acc[2][2], w2.y, x2.y);
        fma2(acc[3][2], w3.x, x2.x); fma2(acc[3][2], w3.y, x2.y);
        fma2(acc[0][3], w0.x, x3.x); fma2(acc[0][3], w0.y, x3.y);
        fma2(acc[1][3], w1.x, x3.x); fma2(acc[1][3], w1.y, x3.y);
        fma2(acc[2][3], w2.x, x3.x); fma2(acc[2][3], w2.y, x3.y);
        fma2(acc[3][3], w3.x, x3.x); fma2(acc[3][3], w3.y, x3.y);
    }

    float b0 = bs[kq * 4 + 0], b1 = bs[kq * 4 + 1];
    float b2 = bs[kq * 4 + 2], b3 = bs[kq * 4 + 3];
    float4* Yg = (float4*)Y;
#pragma unroll
    for (int rr = 0; rr < 4; rr++) {
        int r = rg + 16 * rr;
        float4 o;
        o.x = red2(acc[0][rr]) + b0;
        o.y = red2(acc[1][rr]) + b1;
        o.z = red2(acc[2][rr]) + b2;
        o.w = red2(acc[3][rr]) + b3;
        Yg[(row0 + r) * 25 + kq] = o;
    }
}

// ---------------------------------------------------------------------------
// 3) recurrent scan: h_new = tanh(xin[t] + h @ Wh^T), in-place on XY.
// Wh row lives in REGISTERS (thread k holds W[k][0..99]); h read via smem
// broadcast only. 2 batch rows/block, 256 blocks. FFMA2 -> 100 packed
// FMA/thread/step. One __syncthreads per step (double-buffered h).
// ---------------------------------------------------------------------------
__global__ void __launch_bounds__(128, 2) k_rnn(float* __restrict__ XY,
                                                const float* __restrict__ W,
                                                float* __restrict__ hout) {
    __shared__ __align__(16) float hs[2][2][104];

    int tid = threadIdx.x;
    int kk = (tid < HH) ? tid : (HH - 1);

    ulonglong2 wv[25];                       // W[kk][0..99] packed pairs
    const ulonglong2* Wg = (const ulonglong2*)W;
#pragma unroll
    for (int i = 0; i < 25; i++) wv[i] = Wg[kk * 25 + i];

    if (tid < 104) { hs[0][0][tid] = 0.f; hs[0][1][tid] = 0.f; }
    __syncthreads();

    int b0 = blockIdx.x * 2;
    const size_t st = (size_t)BB * HH;
    const float* px = XY + (size_t)b0 * HH + kk;

    float c0 = px[0], c1 = px[HH];
    int p = 0;

    for (int t = 0; t < TT; t++) {
        size_t tn = (size_t)((t + 1 < TT) ? t + 1 : t) * st;
        float n0 = px[tn], n1 = px[tn + HH];   // prefetch next xin

        ull a0a = 0ull, a0b = 0ull, a1a = 0ull, a1b = 0ull;
        const ulonglong2* h0p = (const ulonglong2*)&hs[p][0][0];
        const ulonglong2* h1p = (const ulonglong2*)&hs[p][1][0];
#pragma unroll
        for (int j = 0; j < 25; j++) {
            ulonglong2 w = wv[j];
            ulonglong2 h0 = h0p[j];            // pure broadcast loads
            ulonglong2 h1 = h1p[j];
            fma2(a0a, w.x, h0.x); fma2(a0b, w.y, h0.y);
            fma2(a1a, w.x, h1.x); fma2(a1b, w.y, h1.y);
        }
        float a0 = ftanh(red2(a0a) + red2(a0b) + c0);
        float a1 = ftanh(red2(a1a) + red2(a1b) + c1);

        if (tid < HH) {
            hs[p ^ 1][0][tid] = a0;
            hs[p ^ 1][1][tid] = a1;
            float* py = XY + (size_t)t * st + (size_t)b0 * HH + tid;
            py[0] = a0; py[HH] = a1;
        }
        __syncthreads();
        p ^= 1;
        c0 = n0; c1 = n1;
    }

    if (tid < HH) {
        hout[(size_t)b0 * HH + tid]       = hs[p][0][tid];
        hout[(size_t)(b0 + 1) * HH + tid] = hs[p][1][tid];
    }
}

// ---------------------------------------------------------------------------
// 4) decoder: logits[b][t][v] = dot(ys[t][b][:], Wd[v][:]) + bd[v]
// 256 thr = 16 v-quads (vq=tid/16, V padded 64) x 16 row-groups, 64 rows/blk.
// ---------------------------------------------------------------------------
__global__ void __launch_bounds__(256, 3) k_dec(const float* __restrict__ Ys,
                                                const float* __restrict__ Wd,
                                                const float* __restrict__ bd,
                                                float* __restrict__ out) {
    extern __shared__ float sm[];
    float* Ws = sm;            // [64][100] zero-padded
    float* Xs = sm + 6400;     // [64][100]
    float* bs = sm + 12800;    // [64]

    int tid = threadIdx.x;
    for (int i = tid; i < 6400; i += 256) Ws[i] = (i < VV * HH) ? Wd[i] : 0.f;
    if (tid < 64) bs[tid] = (tid < VV) ? bd[tid] : 0.f;

    size_t row0 = (size_t)blockIdx.x * 64;
    float4* Xs4 = (float4*)Xs;
    const float4* Yg = (const float4*)Ys;
    for (int i = tid; i < 1600; i += 256) Xs4[i] = Yg[row0 * 25 + i];
    __syncthreads();

    int vq = tid / 16;   // 0..15
    int rg = tid % 16;

    const ulonglong2* Wu = (const ulonglong2*)Ws;
    const ulonglong2* Xu = (const ulonglong2*)Xs;

    ull acc[4][4];
#pragma unroll
    for (int c = 0; c < 4; c++)
#pragma unroll
        for (int r = 0; r < 4; r++) acc[c][r] = 0ull;

#pragma unroll 5
    for (int j4 = 0; j4 < 25; j4++) {
        ulonglong2 w0 = Wu[(vq * 4 + 0) * 25 + j4];
        ulonglong2 w1 = Wu[(vq * 4 + 1) * 25 + j4];
        ulonglong2 w2 = Wu[(vq * 4 + 2) * 25 + j4];
        ulonglong2 w3 = Wu[(vq * 4 + 3) * 25 + j4];
        ulonglong2 x0 = Xu[(rg +  0) * 25 + j4];
        ulonglong2 x1 = Xu[(rg + 16) * 25 + j4];
        ulonglong2 x2 = Xu[(rg + 32) * 25 + j4];
        ulonglong2 x3 = Xu[(rg + 48) * 25 + j4];
        fma2(acc[0][0], w0.x, x0.x); fma2(acc[0][0], w0.y, x0.y);
        fma2(acc[1][0], w1.x, x0.x); fma2(acc[1][0], w1.y, x0.y);
        fma2(acc[2][0], w2.x, x0.x); fma2(acc[2][0], w2.y, x0.y);
        fma2(acc[3][0], w3.x, x0.x); fma2(acc[3][0], w3.y, x0.y);
        fma2(acc[0][1], w0.x, x1.x); fma2(acc[0][1], w0.y, x1.y);
        fma2(acc[1][1], w1.x, x1.x); fma2(acc[1][1], w1.y, x1.y);
        fma2(acc[2][1], w2.x, x1.x); fma2(acc[2][1], w2.y, x1.y);
        fma2(acc[3][1], w3.x, x1.x); fma2(acc[3][1], w3.y, x1.y);
        fma2(acc[0][2], w0.x, x2.x); fma2(acc[0][2], w0.y, x2.y);
        fma2(acc[1][2], w1.x, x2.x); fma2(acc[1][2], w1.y, x2.y);
        fma2(acc[2][2], w2.x, x2.x); fma2(acc[2][2], w2.y, x2.y);
        fma2(acc[3][2], w3.x, x2.x); fma2(acc[3][2], w3.y, x2.y);
        fma2(acc[0][3], w0.x, x3.x); fma2(acc[0][3], w0.y, x3.y);
        fma2(acc[1][3], w1.x, x3.x); fma2(acc[1][3], w1.y, x3.y);
        fma2(acc[2][3], w2.x, x3.x); fma2(acc[2][3], w2.y, x3.y);
        fma2(acc[3][3], w3.x, x3.x); fma2(acc[3][3], w3.y, x3.y);
    }

    int v0 = vq * 4;
    float bb0 = bs[v0], bb1 = bs[v0 + 1], bb2 = bs[v0 + 2], bb3 = bs[v0 + 3];
#pragma unroll
    for (int rr = 0; rr < 4; rr++) {
        size_t row = row0 + rg + 16 * rr;   // = t*BB + b
        size_t t = row >> 9;
        size_t b = row & 511;
        float* o = out + (b * TT + t) * VV + v0;
        o[0] = red2(acc[0][rr]) + bb0;
        o[1] = red2(acc[1][rr]) + bb1;
        if (v0 + 2 < VV) {
            o[2] = red2(acc[2][rr]) + bb2;
            o[3] = red2(acc[3][rr]) + bb3;
        }
    }
}

// ---------------------------------------------------------------------------
extern "C" void kernel_launch(void* const* d_in, const int* in_sizes, int n_in,
                              void* d_out, int out_size) {
    const int*   ids   = (const int*)d_in[0];
    const float* emb   = (const float*)d_in[1];
    const float* W_ih  = (const float*)d_in[2];   // [3][100][100]
    const float* W_hh  = (const float*)d_in[3];   // [3][100][100]
    const float* b_ih  = (const float*)d_in[4];   // [3][100]
    const float* b_hh  = (const float*)d_in[5];   // [3][100]
    const float* W_dec = (const float*)d_in[6];   // [62][100]
    const float* b_dec = (const float*)d_in[7];   // [62]
    float* out = (float*)d_out;

    float *bufA, *bufB;
    cudaGetSymbolAddress((void**)&bufA, g_bufA);
    cudaGetSymbolAddress((void**)&bufB, g_bufB);

    const int proj_smem = 16500 * (int)sizeof(float);   // 66 KB
    const int dec_smem  = 12864 * (int)sizeof(float);   // ~50 KB
    cudaFuncSetAttribute(k_proj, cudaFuncAttributeMaxDynamicSharedMemorySize, proj_smem);
    cudaFuncSetAttribute(k_dec,  cudaFuncAttributeMaxDynamicSharedMemorySize, dec_smem);

    float* hid = out + (size_t)BB * TT * VV;
    const int NB = (TT * BB) / 64;   // 8192

    k_gather<<<(TT * BB * 25 + 255) / 256, 256>>>(ids, emb, bufA);

    // layer 0
    k_proj<<<NB, 400, proj_smem>>>(bufA, W_ih, b_ih, b_hh, bufB);
    k_rnn<<<BB / 2, 128>>>(bufB, W_hh, hid);
    // layer 1
    k_proj<<<NB, 400, proj_smem>>>(bufB, W_ih + 10000, b_ih + 100, b_hh + 100, bufA);
    k_rnn<<<BB / 2, 128>>>(bufA, W_hh + 10000, hid + (size_t)BB * HH);
    // layer 2
    k_proj<<<NB, 400, proj_smem>>>(bufA, W_ih + 20000, b_ih + 200, b_hh + 200, bufB);
    k_rnn<<<BB / 2, 128>>>(bufB, W_hh + 20000, hid + 2 * (size_t)BB * HH);

    k_dec<<<NB, 256, dec_smem>>>(bufB, W_dec, b_dec, out);
}